// round 17
// baseline (speedup 1.0000x reference)
#include <cuda_runtime.h>
#include <cuda_fp16.h>
#include <math.h>

// Problem constants
#define B  32
#define O  64
#define I  2048
#define VO 32
#define VI 16

#define ITER 8            // i's per p0 CTA
#define NIBLK (I / ITER)  // 256 i-blocks

typedef unsigned long long u64;

// Scratch (device globals: no allocation allowed)
__device__ __half g_uhat[(size_t)B * I * O * VO];          // fp16, 256 MB
__device__ float g_S0part[(size_t)NIBLK * B * O * VO];     // 67 MB partial S0
__device__ float g_S1[B * O * VO];
__device__ float g_S2[B * O * VO];
__device__ float g_Vacc[B * O * VO];                       // v0, then v0+v1

// ---------------------------------------------------------------------------
// helpers
// ---------------------------------------------------------------------------
__device__ __forceinline__ unsigned int smem_u32(const void* p) {
    return (unsigned int)__cvta_generic_to_shared(p);
}
__device__ __forceinline__ void mma_16816(float* d, const unsigned int* a,
                                          const unsigned int* b) {
    asm volatile(
        "mma.sync.aligned.m16n8k16.row.col.f32.f16.f16.f32 "
        "{%0,%1,%2,%3},{%4,%5,%6,%7},{%8,%9},{%0,%1,%2,%3};"
        : "+f"(d[0]), "+f"(d[1]), "+f"(d[2]), "+f"(d[3])
        : "r"(a[0]), "r"(a[1]), "r"(a[2]), "r"(a[3]), "r"(b[0]), "r"(b[1]));
}
// NON-trans ldmatrix: SMEM rows are n (=v), cols are k (=u) -> B fragment
__device__ __forceinline__ void ldmx2(unsigned int& b0, unsigned int& b1,
                                      unsigned int saddr) {
    asm volatile("ldmatrix.sync.aligned.m8n8.x2.shared.b16 {%0,%1},[%2];"
                 : "=r"(b0), "=r"(b1) : "r"(saddr));
}
__device__ __forceinline__ unsigned int pack_h(float a, float b) {
    __half2 p = __halves2half2(__float2half_rn(a), __float2half_rn(b));
    return *(unsigned int*)&p;
}
__device__ __forceinline__ unsigned int pack_l(float a, float b, unsigned int hp) {
    float2 hf = __half22float2(*(__half2*)&hp);
    __half2 p = __halves2half2(__float2half_rn(a - hf.x), __float2half_rn(b - hf.y));
    return *(unsigned int*)&p;
}

// ---------------------------------------------------------------------------
// Zero the atomic accumulators (graph replays reuse scratch)
// ---------------------------------------------------------------------------
__global__ void zero_kernel() {
    int idx = blockIdx.x * blockDim.x + threadIdx.x;
    if (idx < B * O * VO) {
        g_S1[idx] = 0.0f;
        g_S2[idx] = 0.0f;
    }
}

// ---------------------------------------------------------------------------
// P0 (tensor cores, mma.sync, amortized, fused S0 partials) — R12 proven.
// ---------------------------------------------------------------------------
__global__ void __launch_bounds__(256) p0_mma(const float* __restrict__ W,
                                              const float* __restrict__ x) {
    __shared__ __half Whs[8 * 32 * 24];  // 12 KB  per-warp W-hi tile
    __shared__ __half Wls[8 * 32 * 24];  // 12 KB  per-warp W-lo tile
    __shared__ float  Xs[32 * 24];       //  3 KB  x fp32 (padded rows)
    __shared__ __half Dout[32 * 264];    // 16.5 KB output staging (padded)

    const int iblk = blockIdx.x;
    const int i0  = iblk * ITER;
    const int o0  = blockIdx.y * 8;
    const int tid = threadIdx.x;
    const int wid = tid >> 5;
    const int lane = tid & 31;

    const int gid = lane >> 2, tig = lane & 3;
    const int lr = lane & 7, sel = (lane >> 3) & 1;

    const float4* wbase = (const float4*)(W + ((size_t)(o0 + wid) * I + i0) * 512);
    const int xb = tid >> 2, xq = tid & 3;

    float facc[4][8];
#pragma unroll
    for (int j = 0; j < 4; j++)
#pragma unroll
        for (int e = 0; e < 8; e++) facc[j][e] = 0.f;

    // ---- prologue: prefetch i0 ----
    float4 w4[4];
#pragma unroll
    for (int j = 0; j < 4; j++) w4[j] = wbase[j * 32 + lane];
    float4 x4;
    if (tid < 128)
        x4 = *(const float4*)(x + ((size_t)xb * I + i0) * VI + xq * 4);

    for (int it = 0; it < ITER; it++) {
        const int i = i0 + it;

        // ---- stage from prefetch regs ----
#pragma unroll
        for (int j = 0; j < 4; j++) {
            int c = j * 32 + lane;
            int v = c >> 2, q = c & 3;
            unsigned int h0 = pack_h(w4[j].x, w4[j].y);
            unsigned int h1 = pack_h(w4[j].z, w4[j].w);
            unsigned int l0 = pack_l(w4[j].x, w4[j].y, h0);
            unsigned int l1 = pack_l(w4[j].z, w4[j].w, h1);
            *(uint2*)&Whs[(wid * 32 + v) * 24 + q * 4] = make_uint2(h0, h1);
            *(uint2*)&Wls[(wid * 32 + v) * 24 + q * 4] = make_uint2(l0, l1);
        }
        if (tid < 128)
            *(float4*)&Xs[xb * 24 + xq * 4] = x4;

        // ---- prefetch next i ----
        if (it + 1 < ITER) {
            const float4* wb2 = wbase + (size_t)(it + 1) * 128;
#pragma unroll
            for (int j = 0; j < 4; j++) w4[j] = wb2[j * 32 + lane];
            if (tid < 128)
                x4 = *(const float4*)(x + ((size_t)xb * I + (i + 1)) * VI + xq * 4);
        }
        __syncthreads();

        // ---- A fragments (proven R9 mapping) ----
        unsigned int Ah[2][4], Al[2][4];
#pragma unroll
        for (int mt = 0; mt < 2; mt++) {
            int r0 = gid + mt * 16, r1 = r0 + 8;
            float2 x00 = *(float2*)&Xs[r0 * 24 + 2 * tig];
            float2 x01 = *(float2*)&Xs[r0 * 24 + 2 * tig + 8];
            float2 x10 = *(float2*)&Xs[r1 * 24 + 2 * tig];
            float2 x11 = *(float2*)&Xs[r1 * 24 + 2 * tig + 8];
            Ah[mt][0] = pack_h(x00.x, x00.y);
            Ah[mt][1] = pack_h(x10.x, x10.y);
            Ah[mt][2] = pack_h(x01.x, x01.y);
            Ah[mt][3] = pack_h(x11.x, x11.y);
            Al[mt][0] = pack_l(x00.x, x00.y, Ah[mt][0]);
            Al[mt][1] = pack_l(x10.x, x10.y, Ah[mt][1]);
            Al[mt][2] = pack_l(x01.x, x01.y, Ah[mt][2]);
            Al[mt][3] = pack_l(x11.x, x11.y, Ah[mt][3]);
        }

        // ---- MMA + epilogue STS into Dout ----
#pragma unroll
        for (int nt = 0; nt < 4; nt++) {
            unsigned int bh[2], bl[2];
            ldmx2(bh[0], bh[1],
                  smem_u32(&Whs[(wid * 32 + nt * 8 + lr) * 24 + sel * 8]));
            ldmx2(bl[0], bl[1],
                  smem_u32(&Wls[(wid * 32 + nt * 8 + lr) * 24 + sel * 8]));
#pragma unroll
            for (int mt = 0; mt < 2; mt++) {
                float d[4] = {0.f, 0.f, 0.f, 0.f};
                mma_16816(d, Ah[mt], bh);
                mma_16816(d, Al[mt], bh);
                mma_16816(d, Ah[mt], bl);

                int v  = 2 * tig + nt * 8;
                int b0 = gid + mt * 16;
                *(unsigned int*)&Dout[b0 * 264 + wid * 32 + v] = pack_h(d[0], d[1]);
                *(unsigned int*)&Dout[(b0 + 8) * 264 + wid * 32 + v] = pack_h(d[2], d[3]);
            }
        }
        __syncthreads();

        // ---- coalesced store + S0 partial accumulation ----
#pragma unroll
        for (int j = 0; j < 4; j++) {
            int c = j * 256 + tid;
            int b = c >> 5, k = c & 31;
            uint4 val = *(uint4*)((char*)Dout + b * 528 + k * 16);
            __half* dst = g_uhat + (((size_t)b * I + i) * O + o0) * VO + k * 8;
            __stcs((uint4*)dst, val);

            float2 f0 = __half22float2(*(const __half2*)&val.x);
            float2 f1 = __half22float2(*(const __half2*)&val.y);
            float2 f2 = __half22float2(*(const __half2*)&val.z);
            float2 f3 = __half22float2(*(const __half2*)&val.w);
            facc[j][0] += f0.x; facc[j][1] += f0.y;
            facc[j][2] += f1.x; facc[j][3] += f1.y;
            facc[j][4] += f2.x; facc[j][5] += f2.y;
            facc[j][6] += f3.x; facc[j][7] += f3.y;
        }
    }

    // ---- flush S0 partials: part[iblk][b][o][v], coalesced ----
#pragma unroll
    for (int j = 0; j < 4; j++) {
        int c = j * 256 + tid;
        int b = c >> 5, k = c & 31;
        float* dst = g_S0part +
            (((size_t)iblk * B + b) * O + (o0 + (k >> 2))) * VO + (k & 3) * 8;
        *(float4*)dst       = make_float4(facc[j][0], facc[j][1], facc[j][2], facc[j][3]);
        *(float4*)(dst + 4) = make_float4(facc[j][4], facc[j][5], facc[j][6], facc[j][7]);
    }
}

// ---------------------------------------------------------------------------
// P1/P2 v7: (o, v-half) split + 8-i batching. CTA = 128 thr = 4 warps = one
// (b, 32-i chunk), 4 batches of 8 i's. Per batch: 16 independent uint4 loads
// (256B/thread in flight), 8 independent dots, 8 INTERLEAVED shuffle reduces
// (chain amortized 8x), ONE barrier (double-buffered wsum), 8 accumulates.
// Softmax without max-shift (|d| <~ 3; exp cannot overflow fp32).
// ---------------------------------------------------------------------------
__global__ void __launch_bounds__(128) p1_kernel(int pass) {
    __shared__ float wsum[2][4][8];   // [buf][warp][t]

    const int cta = blockIdx.x;
    const int tid = threadIdx.x;
    const int warp = tid >> 5;
    const int lane = tid & 31;
    const int b = cta >> 6;               // 32 b's
    const int i0 = (cta & 63) * 32;       // 64 chunks of 32 i's
    const int o = warp * 16 + (lane >> 1);
    const int vh = lane & 1;              // v in [vh*16, vh*16+16)
    float* Sout = (pass == 1) ? g_S1 : g_S2;

    // Vacc half-row for this (o, vh): 16 floats
    float va[16];
    {
        const float4* vp = (const float4*)(g_Vacc + (size_t)(b * O + o) * VO + vh * 16);
#pragma unroll
        for (int j = 0; j < 4; j++) {
            float4 t4 = vp[j];
            va[4 * j + 0] = t4.x; va[4 * j + 1] = t4.y;
            va[4 * j + 2] = t4.z; va[4 * j + 3] = t4.w;
        }
    }

    float sa[16];
#pragma unroll
    for (int v = 0; v < 16; v++) sa[v] = 0.f;

    // half-row base (in uint4): ((b*I+i)*O + o)*4 + vh*2
    const uint4* up = (const uint4*)g_uhat;
    const size_t rbase = (((size_t)b * I + i0) * O + o) * 4 + (size_t)vh * 2;
    const size_t rstride = (size_t)O * 4;   // per-i

    for (int ib = 0; ib < 4; ib++) {
        // ---- load batch: 8 i's, 16 independent 16B loads ----
        uint4 c0[8], c1[8];
#pragma unroll
        for (int t = 0; t < 8; t++) {
            size_t rb = rbase + (size_t)(ib * 8 + t) * rstride;
            c0[t] = __ldcs(up + rb + 0);
            c1[t] = __ldcs(up + rb + 1);
        }

        // ---- 8 independent half-dots ----
        float d[8];
#pragma unroll
        for (int t = 0; t < 8; t++) {
            unsigned int r[8] = {c0[t].x, c0[t].y, c0[t].z, c0[t].w,
                                 c1[t].x, c1[t].y, c1[t].z, c1[t].w};
            float dd = 0.f;
#pragma unroll
            for (int j = 0; j < 8; j++) {
                float2 f = __half22float2(*(const __half2*)&r[j]);
                dd = fmaf(f.x, va[2 * j + 0], dd);
                dd = fmaf(f.y, va[2 * j + 1], dd);
            }
            d[t] = dd;
        }
        // complete dots with partner lane (8 independent shfls)
#pragma unroll
        for (int t = 0; t < 8; t++)
            d[t] += __shfl_xor_sync(0xffffffffu, d[t], 1);

        // ---- exp + interleaved warp reduces ----
        float e[8], es[8];
#pragma unroll
        for (int t = 0; t < 8; t++) { e[t] = __expf(d[t]); es[t] = e[t]; }
#pragma unroll
        for (int off = 16; off; off >>= 1) {
#pragma unroll
            for (int t = 0; t < 8; t++)
                es[t] += __shfl_xor_sync(0xffffffffu, es[t], off);
        }
        if (lane == 0) {
#pragma unroll
            for (int t = 0; t < 8; t++)
                wsum[ib & 1][warp][t] = es[t];   // = 2 * sum over warp's 16 o's
        }
        __syncthreads();

        // ---- coefficients + accumulate (8 i's) ----
#pragma unroll
        for (int t = 0; t < 8; t++) {
            float tot = (wsum[ib & 1][0][t] + wsum[ib & 1][1][t] +
                         wsum[ib & 1][2][t] + wsum[ib & 1][3][t]) * 0.5f;
            float c = e[t] * __frcp_rn(tot);
            unsigned int r[8] = {c0[t].x, c0[t].y, c0[t].z, c0[t].w,
                                 c1[t].x, c1[t].y, c1[t].z, c1[t].w};
#pragma unroll
            for (int j = 0; j < 8; j++) {
                float2 f = __half22float2(*(const __half2*)&r[j]);
                sa[2 * j + 0] = fmaf(c, f.x, sa[2 * j + 0]);
                sa[2 * j + 1] = fmaf(c, f.y, sa[2 * j + 1]);
            }
        }
        // (no second barrier: buffer ib&1 is rewritten at ib+2, after the
        //  ib+1 barrier, by which time these reads are done)
    }

    float* sp = Sout + (size_t)(b * O + o) * VO + vh * 16;
#pragma unroll
    for (int v = 0; v < 16; v++)
        atomicAdd(&sp[v], sa[v]);
}

// ---------------------------------------------------------------------------
// Squash. which==0: reduce g_S0part over 256 i-blocks, v0=squash(S0/64),
//                   Vacc=v0.
//         which==1: v1=squash(S1), Vacc+=v1.
//         which==2: out=squash(S2).
// ---------------------------------------------------------------------------
__global__ void kv_kernel(int which, float* __restrict__ out) {
    int wid = threadIdx.x >> 5;
    int lane = threadIdx.x & 31;
    int pair = blockIdx.x * (blockDim.x >> 5) + wid;
    if (pair >= B * O) return;
    int idx = pair * VO + lane;

    float s;
    if (which == 0) {
        const float* pp = g_S0part + (size_t)pair * VO + lane;
        const size_t stride = (size_t)B * O * VO;
        float acc = 0.f;
#pragma unroll 8
        for (int k = 0; k < NIBLK; k++)
            acc += __ldcs(pp + (size_t)k * stride);
        s = acc * (1.0f / (float)O);
    } else if (which == 1) {
        s = g_S1[idx];
    } else {
        s = g_S2[idx];
    }

    float sq = s * s;
#pragma unroll
    for (int off = 16; off; off >>= 1)
        sq += __shfl_xor_sync(0xffffffffu, sq, off);

    float scale = (sq / (1.0f + sq)) * rsqrtf(sq + 1e-8f);
    float v = s * scale;

    if (which == 0)      g_Vacc[idx] = v;
    else if (which == 1) g_Vacc[idx] += v;
    else                 out[idx] = v;
}

// ---------------------------------------------------------------------------
extern "C" void kernel_launch(void* const* d_in, const int* in_sizes, int n_in,
                              void* d_out, int out_size) {
    const float* x;
    const float* W;
    if (in_sizes[0] == B * I * VI) {
        x = (const float*)d_in[0];
        W = (const float*)d_in[1];
    } else {
        x = (const float*)d_in[1];
        W = (const float*)d_in[0];
    }
    float* out = (float*)d_out;

    zero_kernel<<<(B * O * VO + 255) / 256, 256>>>();

    // P0: u_hat (fp16) via mma.sync + fused S0 partials
    p0_mma<<<dim3(NIBLK, O / 8), 256>>>(W, x);

    // Iteration 0: reduce S0 partials + squash
    kv_kernel<<<64, 1024>>>(0, out);   // v0 = squash(S0/64); Vacc = v0

    // Iteration 1: logits = u_hat . v0   (raw launch idx 5 -> ncu target)
    p1_kernel<<<2048, 128>>>(1);
    kv_kernel<<<64, 1024>>>(1, out);   // v1 = squash(S1); Vacc = v0 + v1

    // Iteration 2: logits = u_hat . (v0 + v1)
    p1_kernel<<<2048, 128>>>(2);
    kv_kernel<<<64, 1024>>>(2, out);   // out = squash(S2)
}